// round 5
// baseline (speedup 1.0000x reference)
#include <cuda_runtime.h>
#include <cuda_fp16.h>
#include <cstdint>

// NT-Xent loss, symmetric-Gram fused pipeline (fallback-HMMA path; tcgen05 is
// gated off by the harness's compute_103 PTX stage):
//   normalize(fp16 rows + inv-norms) -> triangular f16 mma.sync Gram tiles
//   (each block emits row- AND column-partials) -> fused loss+block-reduce
//   -> final warp mean.
// N = 8192, D = 128, T = 0.5 (logit scale 2; cos<=1 so lse needs no max).

#define N_TOT  8192
#define DIM    128
#define B_HALF 4096
#define BM     128
#define BN     128
#define LDS    136              // smem row stride in halves (272B, 16B-aligned)
#define NJT    (N_TOT / BN)     // 64 tile rows/cols
#define NTILE  (NJT * (NJT + 1) / 2)   // 2080 upper-triangle tiles

#define SM_A    0
#define SM_B    (BM * LDS * 2)              // 34816
#define SM_RED  (SM_B + BN * LDS * 2)       // 69632 : float red[2][128]
#define SM_CRED (SM_RED + 1024)             // 70656 : float colred[4][128]
#define SMEM_SZ (SM_CRED + 2048)            // 72704 bytes

__device__ __half g_zn_h[N_TOT * DIM];      // normalized rows, fp16 (MMA operands)
__device__ float  g_invn[N_TOT];            // 1/||z_r|| (positive-pair scaling)
__device__ float  g_partial[NJT * N_TOT];   // [tile][row] partial exp-sums
__device__ float  g_bsum[64];               // per-block loss sums

// ---------------------------------------------------------------------------
// Kernel 1: row normalization. One warp per row; fp16 rows + inverse norm.
// ---------------------------------------------------------------------------
__global__ void k_normalize(const float* __restrict__ zi, const float* __restrict__ zj) {
    int warp = (blockIdx.x * blockDim.x + threadIdx.x) >> 5;
    int lane = threadIdx.x & 31;
    if (warp >= N_TOT) return;
    const float* src = (warp < B_HALF) ? (zi + warp * DIM) : (zj + (warp - B_HALF) * DIM);
    float4 v = ((const float4*)src)[lane];
    float ss = v.x * v.x + v.y * v.y + v.z * v.z + v.w * v.w;
    #pragma unroll
    for (int o = 16; o; o >>= 1) ss += __shfl_xor_sync(0xffffffffu, ss, o);
    float inv = rsqrtf(ss);
    __half2* hdst = (__half2*)(g_zn_h + warp * DIM);
    hdst[lane * 2]     = __floats2half2_rn(v.x * inv, v.y * inv);
    hdst[lane * 2 + 1] = __floats2half2_rn(v.z * inv, v.w * inv);
    if (lane == 0) g_invn[warp] = inv;
}

// ---------------------------------------------------------------------------
// MMA helpers
// ---------------------------------------------------------------------------
__device__ __forceinline__ void ldsm_x4(uint32_t addr, uint32_t& r0, uint32_t& r1,
                                        uint32_t& r2, uint32_t& r3) {
    asm volatile("ldmatrix.sync.aligned.m8n8.x4.shared.b16 {%0,%1,%2,%3}, [%4];"
                 : "=r"(r0), "=r"(r1), "=r"(r2), "=r"(r3) : "r"(addr));
}

__device__ __forceinline__ void mma16816(float* c, const uint32_t* a, const uint32_t* b) {
    asm volatile("mma.sync.aligned.m16n8k16.row.col.f32.f16.f16.f32 "
                 "{%0,%1,%2,%3}, {%4,%5,%6,%7}, {%8,%9}, {%0,%1,%2,%3};"
                 : "+f"(c[0]), "+f"(c[1]), "+f"(c[2]), "+f"(c[3])
                 : "r"(a[0]), "r"(a[1]), "r"(a[2]), "r"(a[3]), "r"(b[0]), "r"(b[1]));
}

// ---------------------------------------------------------------------------
// Kernel 2: 128x128 Gram tile, 1D triangular grid over jt >= it.
// 256 threads = 8 warps (4 in M x 2 in N), warp tile 32x64.
// Emits row-partials (-> g_partial[jt][i-rows]) and, for jt>it,
// column-partials (-> g_partial[it][j-rows]) from the same exp values.
// ---------------------------------------------------------------------------
__global__ void __launch_bounds__(256, 1) k_simexp() {
    // Decode linear tile id -> (it, jt), jt >= it. offset(it) = it*(129-it)/2.
    const int b = blockIdx.x;
    int it = (int)((129.0f - sqrtf(129.0f * 129.0f - 8.0f * (float)b)) * 0.5f);
    if (it < 0) it = 0;
    while (it * (129 - it) / 2 > b) --it;
    while ((it + 1) * (128 - it) / 2 <= b) ++it;
    const int jt = it + (b - it * (129 - it) / 2);

    extern __shared__ char smem[];
    __half* As = (__half*)(smem + SM_A);
    __half* Bs = (__half*)(smem + SM_B);
    float*  red    = (float*)(smem + SM_RED);    // [2][128]
    float*  colred = (float*)(smem + SM_CRED);   // [4][128]

    const int i0 = it * BM, j0 = jt * BN;
    const int tid  = threadIdx.x;
    const int warp = tid >> 5, lane = tid & 31;
    const int wm = warp >> 1;   // 0..3 : 32 rows
    const int wn = warp & 1;    // 0..1 : 64 cols
    const bool diag = (it == jt);

    // Stage full-K operands: 128 rows x 16 x 8-half segments each.
    #pragma unroll
    for (int s = 0; s < 8; s++) {
        int idx = tid + 256 * s;
        int row = idx >> 4, seg = idx & 15;
        *(float4*)(As + row * LDS + seg * 8) =
            *(const float4*)(g_zn_h + (i0 + row) * DIM + seg * 8);
        *(float4*)(Bs + row * LDS + seg * 8) =
            *(const float4*)(g_zn_h + (j0 + row) * DIM + seg * 8);
    }
    __syncthreads();

    float c[2][8][4];
    #pragma unroll
    for (int a = 0; a < 2; a++)
        #pragma unroll
        for (int bq = 0; bq < 8; bq++)
            #pragma unroll
            for (int e = 0; e < 4; e++) c[a][bq][e] = 0.f;

    #pragma unroll
    for (int ks = 0; ks < DIM; ks += 16) {
        uint32_t af[2][4];
        #pragma unroll
        for (int mt = 0; mt < 2; mt++) {
            int row = wm * 32 + mt * 16 + (lane & 15);
            int col = ks + 8 * (lane >> 4);
            uint32_t addr = (uint32_t)__cvta_generic_to_shared(As + row * LDS + col);
            ldsm_x4(addr, af[mt][0], af[mt][1], af[mt][2], af[mt][3]);
        }
        uint32_t bf[8][2];
        #pragma unroll
        for (int np = 0; np < 4; np++) {
            int quad = lane >> 3, within = lane & 7;
            int n = wn * 64 + np * 16 + (quad >> 1) * 8 + within;
            int k = ks + (quad & 1) * 8;
            uint32_t addr = (uint32_t)__cvta_generic_to_shared(Bs + n * LDS + k);
            uint32_t r0, r1, r2, r3;
            ldsm_x4(addr, r0, r1, r2, r3);
            bf[np * 2][0] = r0;     bf[np * 2][1] = r1;
            bf[np * 2 + 1][0] = r2; bf[np * 2 + 1][1] = r3;
        }
        #pragma unroll
        for (int mt = 0; mt < 2; mt++)
            #pragma unroll
            for (int nt = 0; nt < 8; nt++)
                mma16816(c[mt][nt], af[mt], bf[nt]);
    }

    // Epilogue: ev = exp(2*sim); accumulate row sums and column sums.
    float rowsum[4] = {0.f, 0.f, 0.f, 0.f};   // [mt*2+rh]
    float colacc[16];                          // [nt*2+e]
    #pragma unroll
    for (int q = 0; q < 16; q++) colacc[q] = 0.f;

    #pragma unroll
    for (int mt = 0; mt < 2; mt++) {
        #pragma unroll
        for (int nt = 0; nt < 8; nt++) {
            #pragma unroll
            for (int rh = 0; rh < 2; rh++) {
                #pragma unroll
                for (int e = 0; e < 2; e++) {
                    float v = c[mt][nt][rh * 2 + e];
                    float ev = __expf(2.0f * v);
                    if (diag) {
                        int lrow = wm * 32 + mt * 16 + rh * 8 + (lane >> 2);
                        int lcol = wn * 64 + nt * 8 + (lane & 3) * 2 + e;
                        if (lrow == lcol) ev = 0.f;
                    }
                    rowsum[mt * 2 + rh] += ev;
                    colacc[nt * 2 + e]  += ev;
                }
            }
        }
    }

    // Row reduction: sum over the 4 column-lanes of each row.
    #pragma unroll
    for (int mt = 0; mt < 2; mt++) {
        #pragma unroll
        for (int rh = 0; rh < 2; rh++) {
            float s = rowsum[mt * 2 + rh];
            s += __shfl_xor_sync(0xffffffffu, s, 1);
            s += __shfl_xor_sync(0xffffffffu, s, 2);
            if ((lane & 3) == 0) {
                int lrow = wm * 32 + mt * 16 + rh * 8 + (lane >> 2);
                red[wn * BM + lrow] = s;
            }
        }
    }

    // Column reduction: sum over the 8 row-lane-groups.
    #pragma unroll
    for (int q = 0; q < 16; q++) {
        float s = colacc[q];
        s += __shfl_xor_sync(0xffffffffu, s, 4);
        s += __shfl_xor_sync(0xffffffffu, s, 8);
        s += __shfl_xor_sync(0xffffffffu, s, 16);
        colacc[q] = s;
    }
    if (lane < 4) {
        #pragma unroll
        for (int q = 0; q < 16; q++) {
            int lcol = wn * 64 + (q >> 1) * 8 + lane * 2 + (q & 1);
            colred[wm * BN + lcol] = colacc[q];
        }
    }
    __syncthreads();

    if (tid < BM)
        g_partial[jt * N_TOT + i0 + tid] = red[tid] + red[BM + tid];
    if (!diag && tid < BN)
        g_partial[it * N_TOT + j0 + tid] =
            colred[tid] + colred[BN + tid] + colred[2 * BN + tid] + colred[3 * BN + tid];
}

// ---------------------------------------------------------------------------
// Kernel 3 (fused): per-row loss + block partial sum. Grid 64 x 256 threads,
// block owns 128 consecutive rows.
//   Phase 1: coalesced S-sums (lane <-> row; one 128B line per load).
//   Phase 2: warp-per-row fp32 dot from raw inputs * inv-norms.
//   Phase 3: block reduce of 128 losses -> g_bsum[block].
// ---------------------------------------------------------------------------
__global__ void __launch_bounds__(256) k_loss(const float* __restrict__ zi,
                                              const float* __restrict__ zj) {
    __shared__ float sS[2][128];
    __shared__ float wloss[8];
    const int tid = threadIdx.x, lane = tid & 31, warp = tid >> 5;
    const int i0 = blockIdx.x * 128;

    // Phase 1: S partial over 32 tiles per half.
    {
        int rloc = tid & 127, half = tid >> 7;
        int r = i0 + rloc;
        float s = 0.f;
        #pragma unroll
        for (int t = 0; t < 32; t++)
            s += g_partial[(half * 32 + t) * N_TOT + r];
        sS[half][rloc] = s;
    }
    __syncthreads();

    // Phase 2: each warp handles 16 rows; coalesced row reads.
    float acc = 0.f;
    for (int q = 0; q < 16; q++) {
        int rloc = warp * 16 + q;
        int r = i0 + rloc;
        int p = r ^ B_HALF;                       // partner row
        const float* xr = (r < B_HALF) ? (zi + r * DIM) : (zj + (r - B_HALF) * DIM);
        const float* yr = (p < B_HALF) ? (zi + p * DIM) : (zj + (p - B_HALF) * DIM);
        float4 x = ((const float4*)xr)[lane];
        float4 y = ((const float4*)yr)[lane];
        float dot = x.x * y.x + x.y * y.y + x.z * y.z + x.w * y.w;
        #pragma unroll
        for (int o = 16; o; o >>= 1) dot += __shfl_xor_sync(0xffffffffu, dot, o);
        if (lane == 0) {
            float S = sS[0][rloc] + sS[1][rloc];
            acc += logf(S) - 2.0f * dot * g_invn[r] * g_invn[p];
        }
    }
    if (lane == 0) wloss[warp] = acc;
    __syncthreads();

    // Phase 3: reduce 8 warp sums.
    if (warp == 0) {
        float s = (lane < 8) ? wloss[lane] : 0.f;
        #pragma unroll
        for (int o = 4; o; o >>= 1) s += __shfl_xor_sync(0xffffffffu, s, o);
        if (lane == 0) g_bsum[blockIdx.x] = s;
    }
}

// ---------------------------------------------------------------------------
// Kernel 4: final mean over 64 block sums. One warp.
// ---------------------------------------------------------------------------
__global__ void k_final(float* __restrict__ out) {
    int t = threadIdx.x;
    float s = g_bsum[t] + g_bsum[t + 32];
    #pragma unroll
    for (int o = 16; o; o >>= 1) s += __shfl_xor_sync(0xffffffffu, s, o);
    if (t == 0) out[0] = s / (float)N_TOT;
}

// ---------------------------------------------------------------------------
extern "C" void kernel_launch(void* const* d_in, const int* in_sizes, int n_in,
                              void* d_out, int out_size) {
    const float* zi = (const float*)d_in[0];
    const float* zj = (const float*)d_in[1];
    (void)in_sizes; (void)n_in; (void)out_size;

    cudaFuncSetAttribute(k_simexp, cudaFuncAttributeMaxDynamicSharedMemorySize, SMEM_SZ);

    k_normalize<<<N_TOT / 8, 256>>>(zi, zj);
    k_simexp<<<NTILE, 256, SMEM_SZ>>>();
    k_loss<<<64, 256>>>(zi, zj);
    k_final<<<1, 32>>>((float*)d_out);
}

// round 6
// speedup vs baseline: 1.2178x; 1.2178x over previous
#include <cuda_runtime.h>
#include <cuda_fp16.h>
#include <cstdint>

// NT-Xent loss, symmetric-Gram fused pipeline (fallback-HMMA path; tcgen05 is
// gated off by the harness's compute_103 PTX stage):
//   normalize(fp16 rows + inv-norms) -> triangular f16 mma.sync Gram tiles
//   at occ=2 (each block emits row- AND column-partials) -> fused loss +
//   block reduce + last-block final mean.
// N = 8192, D = 128, T = 0.5 (logit scale 2; cos<=1 so lse needs no max).

#define N_TOT  8192
#define DIM    128
#define B_HALF 4096
#define BM     128
#define BN     128
#define LDS    136              // smem row stride in halves (272B, 16B-aligned)
#define NJT    (N_TOT / BN)     // 64 tile rows/cols
#define NTILE  (NJT * (NJT + 1) / 2)   // 2080 upper-triangle tiles

#define SM_A    0
#define SM_B    (BM * LDS * 2)              // 34816
#define SM_RED  (SM_B + BN * LDS * 2)       // 69632 : float red[2][128]
#define SM_CRED (SM_RED + 1024)             // 70656 : float colred[4][128]
#define SMEM_SZ (SM_CRED + 2048)            // 72704 bytes

__device__ __half g_zn_h[N_TOT * DIM];      // normalized rows, fp16 (MMA operands)
__device__ float  g_invn[N_TOT];            // 1/||z_r||
__device__ float  g_partial[NJT * N_TOT];   // [tile][row] partial exp-sums
__device__ float  g_bsum[64];               // per-block loss sums
__device__ int    g_done;                   // k_loss completion counter

// ---------------------------------------------------------------------------
// Kernel 1: row normalization. One warp per row; fp16 rows + inverse norm.
// Also resets the completion counter for this replay.
// ---------------------------------------------------------------------------
__global__ void k_normalize(const float* __restrict__ zi, const float* __restrict__ zj) {
    if (blockIdx.x == 0 && threadIdx.x == 0) g_done = 0;
    int warp = (blockIdx.x * blockDim.x + threadIdx.x) >> 5;
    int lane = threadIdx.x & 31;
    if (warp >= N_TOT) return;
    const float* src = (warp < B_HALF) ? (zi + warp * DIM) : (zj + (warp - B_HALF) * DIM);
    float4 v = ((const float4*)src)[lane];
    float ss = v.x * v.x + v.y * v.y + v.z * v.z + v.w * v.w;
    #pragma unroll
    for (int o = 16; o; o >>= 1) ss += __shfl_xor_sync(0xffffffffu, ss, o);
    float inv = rsqrtf(ss);
    __half2* hdst = (__half2*)(g_zn_h + warp * DIM);
    hdst[lane * 2]     = __floats2half2_rn(v.x * inv, v.y * inv);
    hdst[lane * 2 + 1] = __floats2half2_rn(v.z * inv, v.w * inv);
    if (lane == 0) g_invn[warp] = inv;
}

// ---------------------------------------------------------------------------
// MMA helpers
// ---------------------------------------------------------------------------
__device__ __forceinline__ void ldsm_x4(uint32_t addr, uint32_t& r0, uint32_t& r1,
                                        uint32_t& r2, uint32_t& r3) {
    asm volatile("ldmatrix.sync.aligned.m8n8.x4.shared.b16 {%0,%1,%2,%3}, [%4];"
                 : "=r"(r0), "=r"(r1), "=r"(r2), "=r"(r3) : "r"(addr));
}

__device__ __forceinline__ void mma16816(float* c, const uint32_t* a, const uint32_t* b) {
    asm volatile("mma.sync.aligned.m16n8k16.row.col.f32.f16.f16.f32 "
                 "{%0,%1,%2,%3}, {%4,%5,%6,%7}, {%8,%9}, {%0,%1,%2,%3};"
                 : "+f"(c[0]), "+f"(c[1]), "+f"(c[2]), "+f"(c[3])
                 : "r"(a[0]), "r"(a[1]), "r"(a[2]), "r"(a[3]), "r"(b[0]), "r"(b[1]));
}

// ---------------------------------------------------------------------------
// Kernel 2: 128x128 Gram tile, 1D triangular grid over jt >= it, occ=2.
// 256 threads = 8 warps (4 in M x 2 in N), warp tile 32x64.
// ---------------------------------------------------------------------------
__global__ void __launch_bounds__(256, 2) k_simexp() {
    // Decode linear tile id -> (it, jt), jt >= it. offset(it) = it*(129-it)/2.
    const int b = blockIdx.x;
    int it = (int)((129.0f - sqrtf(129.0f * 129.0f - 8.0f * (float)b)) * 0.5f);
    if (it < 0) it = 0;
    while (it * (129 - it) / 2 > b) --it;
    while ((it + 1) * (128 - it) / 2 <= b) ++it;
    const int jt = it + (b - it * (129 - it) / 2);

    extern __shared__ char smem[];
    __half* As = (__half*)(smem + SM_A);
    __half* Bs = (__half*)(smem + SM_B);
    float*  red    = (float*)(smem + SM_RED);    // [2][128]
    float*  colred = (float*)(smem + SM_CRED);   // [4][128]

    const int i0 = it * BM, j0 = jt * BN;
    const int tid  = threadIdx.x;
    const int warp = tid >> 5, lane = tid & 31;
    const int wm = warp >> 1;   // 0..3 : 32 rows
    const int wn = warp & 1;    // 0..1 : 64 cols
    const bool diag = (it == jt);

    // Stage full-K operands: 128 rows x 16 x 8-half segments each.
    #pragma unroll
    for (int s = 0; s < 8; s++) {
        int idx = tid + 256 * s;
        int row = idx >> 4, seg = idx & 15;
        *(float4*)(As + row * LDS + seg * 8) =
            *(const float4*)(g_zn_h + (i0 + row) * DIM + seg * 8);
        *(float4*)(Bs + row * LDS + seg * 8) =
            *(const float4*)(g_zn_h + (j0 + row) * DIM + seg * 8);
    }
    __syncthreads();

    float c[2][8][4];
    #pragma unroll
    for (int a = 0; a < 2; a++)
        #pragma unroll
        for (int bq = 0; bq < 8; bq++)
            #pragma unroll
            for (int e = 0; e < 4; e++) c[a][bq][e] = 0.f;

    #pragma unroll
    for (int ks = 0; ks < DIM; ks += 16) {
        uint32_t af[2][4];
        #pragma unroll
        for (int mt = 0; mt < 2; mt++) {
            int row = wm * 32 + mt * 16 + (lane & 15);
            int col = ks + 8 * (lane >> 4);
            uint32_t addr = (uint32_t)__cvta_generic_to_shared(As + row * LDS + col);
            ldsm_x4(addr, af[mt][0], af[mt][1], af[mt][2], af[mt][3]);
        }
        uint32_t bf[8][2];
        #pragma unroll
        for (int np = 0; np < 4; np++) {
            int quad = lane >> 3, within = lane & 7;
            int n = wn * 64 + np * 16 + (quad >> 1) * 8 + within;
            int k = ks + (quad & 1) * 8;
            uint32_t addr = (uint32_t)__cvta_generic_to_shared(Bs + n * LDS + k);
            uint32_t r0, r1, r2, r3;
            ldsm_x4(addr, r0, r1, r2, r3);
            bf[np * 2][0] = r0;     bf[np * 2][1] = r1;
            bf[np * 2 + 1][0] = r2; bf[np * 2 + 1][1] = r3;
        }
        #pragma unroll
        for (int mt = 0; mt < 2; mt++)
            #pragma unroll
            for (int nt = 0; nt < 8; nt++)
                mma16816(c[mt][nt], af[mt], bf[nt]);
    }

    // Epilogue: ev = exp(2*sim); accumulate row sums and column sums.
    float rowsum[4] = {0.f, 0.f, 0.f, 0.f};   // [mt*2+rh]
    float colacc[16];                          // [nt*2+e]
    #pragma unroll
    for (int q = 0; q < 16; q++) colacc[q] = 0.f;

    #pragma unroll
    for (int mt = 0; mt < 2; mt++) {
        #pragma unroll
        for (int nt = 0; nt < 8; nt++) {
            #pragma unroll
            for (int rh = 0; rh < 2; rh++) {
                #pragma unroll
                for (int e = 0; e < 2; e++) {
                    float v = c[mt][nt][rh * 2 + e];
                    float ev = __expf(2.0f * v);
                    if (diag) {
                        int lrow = wm * 32 + mt * 16 + rh * 8 + (lane >> 2);
                        int lcol = wn * 64 + nt * 8 + (lane & 3) * 2 + e;
                        if (lrow == lcol) ev = 0.f;
                    }
                    rowsum[mt * 2 + rh] += ev;
                    colacc[nt * 2 + e]  += ev;
                }
            }
        }
    }

    // Row reduction: sum over the 4 column-lanes of each row.
    #pragma unroll
    for (int mt = 0; mt < 2; mt++) {
        #pragma unroll
        for (int rh = 0; rh < 2; rh++) {
            float s = rowsum[mt * 2 + rh];
            s += __shfl_xor_sync(0xffffffffu, s, 1);
            s += __shfl_xor_sync(0xffffffffu, s, 2);
            if ((lane & 3) == 0) {
                int lrow = wm * 32 + mt * 16 + rh * 8 + (lane >> 2);
                red[wn * BM + lrow] = s;
            }
        }
    }

    // Column reduction: sum over the 8 row-lane-groups.
    #pragma unroll
    for (int q = 0; q < 16; q++) {
        float s = colacc[q];
        s += __shfl_xor_sync(0xffffffffu, s, 4);
        s += __shfl_xor_sync(0xffffffffu, s, 8);
        s += __shfl_xor_sync(0xffffffffu, s, 16);
        colacc[q] = s;
    }
    if (lane < 4) {
        #pragma unroll
        for (int q = 0; q < 16; q++) {
            int lcol = wn * 64 + (q >> 1) * 8 + lane * 2 + (q & 1);
            colred[wm * BN + lcol] = colacc[q];
        }
    }
    __syncthreads();

    if (tid < BM)
        g_partial[jt * N_TOT + i0 + tid] = red[tid] + red[BM + tid];
    if (!diag && tid < BN)
        g_partial[it * N_TOT + j0 + tid] =
            colred[tid] + colred[BN + tid] + colred[2 * BN + tid] + colred[3 * BN + tid];
}

// ---------------------------------------------------------------------------
// Kernel 3 (fused): per-row loss + block sum + last-block final mean.
// Grid 64 x 256 threads, block owns 128 consecutive rows.
// ---------------------------------------------------------------------------
__global__ void __launch_bounds__(256) k_loss(const float* __restrict__ zi,
                                              const float* __restrict__ zj,
                                              float* __restrict__ out) {
    __shared__ float sS[2][128];
    __shared__ float wloss[8];
    __shared__ bool  amLast;
    const int tid = threadIdx.x, lane = tid & 31, warp = tid >> 5;
    const int i0 = blockIdx.x * 128;

    // Phase 1: S partials, coalesced (lane <-> row).
    {
        int rloc = tid & 127, half = tid >> 7;
        int r = i0 + rloc;
        float s = 0.f;
        #pragma unroll
        for (int t = 0; t < 32; t++)
            s += g_partial[(half * 32 + t) * N_TOT + r];
        sS[half][rloc] = s;
    }
    __syncthreads();

    // Phase 2: warp-per-row fp32 dots from raw inputs * inv-norms.
    float acc = 0.f;
    for (int q = 0; q < 16; q++) {
        int rloc = warp * 16 + q;
        int r = i0 + rloc;
        int p = r ^ B_HALF;
        const float* xr = (r < B_HALF) ? (zi + r * DIM) : (zj + (r - B_HALF) * DIM);
        const float* yr = (p < B_HALF) ? (zi + p * DIM) : (zj + (p - B_HALF) * DIM);
        float4 x = ((const float4*)xr)[lane];
        float4 y = ((const float4*)yr)[lane];
        float dot = x.x * y.x + x.y * y.y + x.z * y.z + x.w * y.w;
        #pragma unroll
        for (int o = 16; o; o >>= 1) dot += __shfl_xor_sync(0xffffffffu, dot, o);
        if (lane == 0) {
            float S = sS[0][rloc] + sS[1][rloc];
            acc += logf(S) - 2.0f * dot * g_invn[r] * g_invn[p];
        }
    }
    if (lane == 0) wloss[warp] = acc;
    __syncthreads();

    if (warp == 0) {
        float s = (lane < 8) ? wloss[lane] : 0.f;
        #pragma unroll
        for (int o = 4; o; o >>= 1) s += __shfl_xor_sync(0xffffffffu, s, o);
        if (lane == 0) {
            g_bsum[blockIdx.x] = s;
            __threadfence();
            amLast = (atomicAdd(&g_done, 1) == 63);
        }
    }
    __syncthreads();

    // Last block: deterministic fixed-order sum of the 64 block results.
    if (amLast && warp == 0) {
        float s = g_bsum[lane] + g_bsum[lane + 32];
        #pragma unroll
        for (int o = 16; o; o >>= 1) s += __shfl_xor_sync(0xffffffffu, s, o);
        if (lane == 0) out[0] = s / (float)N_TOT;
    }
}

// ---------------------------------------------------------------------------
extern "C" void kernel_launch(void* const* d_in, const int* in_sizes, int n_in,
                              void* d_out, int out_size) {
    const float* zi = (const float*)d_in[0];
    const float* zj = (const float*)d_in[1];
    (void)in_sizes; (void)n_in; (void)out_size;

    cudaFuncSetAttribute(k_simexp, cudaFuncAttributeMaxDynamicSharedMemorySize, SMEM_SZ);

    k_normalize<<<N_TOT / 8, 256>>>(zi, zj);
    k_simexp<<<NTILE, 256, SMEM_SZ>>>();
    k_loss<<<64, 256>>>(zi, zj, (float*)d_out);
}

// round 8
// speedup vs baseline: 1.3747x; 1.1288x over previous
#include <cuda_runtime.h>
#include <cuda_fp16.h>
#include <cstdint>

// NT-Xent loss, symmetric-Gram fused pipeline (fallback-HMMA; tcgen05 is
// gated off by the harness's compute_103 PTX stage):
//   normalize (fp16 rows + positive-pair logits) -> paired-j f16 mma.sync
//   Gram tiles at occ=2 (row- AND column-partials) -> S-sum + log - pos
//   + last-block mean.
// N = 8192, D = 128, T = 0.5 (logit scale 2; cos<=1 so lse needs no max).

#define N_TOT  8192
#define DIM    128
#define B_HALF 4096
#define BM     128
#define BN     128
#define LDS    136              // smem row stride in halves (272B, 16B-aligned)
#define NJT    (N_TOT / BN)     // 64 tile rows/cols

#define SM_A    0
#define SM_B0   (BM * LDS * 2)              // 34816
#define SM_B1   (SM_B0 + BN * LDS * 2)      // 69632
#define SM_RED  (SM_B1 + BN * LDS * 2)      // 104448 : float red[2][128]
#define SM_CRED (SM_RED + 1024)             // 105472 : float colred[4][128]
#define SMEM_SZ (SM_CRED + 2048)            // 107520 bytes; x2 CTAs = 215KB

__device__ __half g_zn_h[N_TOT * DIM];      // normalized rows, fp16
__device__ float  g_pos[B_HALF];            // positive logits 2*cos(z_i,z_j)
__device__ float  g_partial[NJT * N_TOT];   // [jblock][row] partial exp-sums
__device__ float  g_bsum[64];               // per-block loss sums
__device__ int    g_done;                   // completion counter

// ---------------------------------------------------------------------------
// Kernel 1: one warp per PAIR (z_i[r], z_j[r]): both norms + cross dot.
// ---------------------------------------------------------------------------
__global__ void k_normalize(const float* __restrict__ zi, const float* __restrict__ zj) {
    if (blockIdx.x == 0 && threadIdx.x == 0) g_done = 0;
    int w = (blockIdx.x * blockDim.x + threadIdx.x) >> 5;   // 0..4095
    int lane = threadIdx.x & 31;
    if (w >= B_HALF) return;
    float4 a = ((const float4*)(zi + w * DIM))[lane];
    float4 b = ((const float4*)(zj + w * DIM))[lane];
    float ssi = a.x * a.x + a.y * a.y + a.z * a.z + a.w * a.w;
    float ssj = b.x * b.x + b.y * b.y + b.z * b.z + b.w * b.w;
    float dot = a.x * b.x + a.y * b.y + a.z * b.z + a.w * b.w;
    #pragma unroll
    for (int o = 16; o; o >>= 1) {
        ssi += __shfl_xor_sync(0xffffffffu, ssi, o);
        ssj += __shfl_xor_sync(0xffffffffu, ssj, o);
        dot += __shfl_xor_sync(0xffffffffu, dot, o);
    }
    float invi = rsqrtf(ssi), invj = rsqrtf(ssj);
    __half2* di = (__half2*)(g_zn_h + w * DIM);
    __half2* dj = (__half2*)(g_zn_h + (w + B_HALF) * DIM);
    di[lane * 2]     = __floats2half2_rn(a.x * invi, a.y * invi);
    di[lane * 2 + 1] = __floats2half2_rn(a.z * invi, a.w * invi);
    dj[lane * 2]     = __floats2half2_rn(b.x * invj, b.y * invj);
    dj[lane * 2 + 1] = __floats2half2_rn(b.z * invj, b.w * invj);
    if (lane == 0) g_pos[w] = 2.0f * dot * invi * invj;
}

// ---------------------------------------------------------------------------
// MMA helpers
// ---------------------------------------------------------------------------
__device__ __forceinline__ void ldsm_x4(uint32_t addr, uint32_t& r0, uint32_t& r1,
                                        uint32_t& r2, uint32_t& r3) {
    asm volatile("ldmatrix.sync.aligned.m8n8.x4.shared.b16 {%0,%1,%2,%3}, [%4];"
                 : "=r"(r0), "=r"(r1), "=r"(r2), "=r"(r3) : "r"(addr));
}

__device__ __forceinline__ void mma16816(float* c, const uint32_t* a, const uint32_t* b) {
    asm volatile("mma.sync.aligned.m16n8k16.row.col.f32.f16.f16.f32 "
                 "{%0,%1,%2,%3}, {%4,%5,%6,%7}, {%8,%9}, {%0,%1,%2,%3};"
                 : "+f"(c[0]), "+f"(c[1]), "+f"(c[2]), "+f"(c[3])
                 : "r"(a[0]), "r"(a[1]), "r"(a[2]), "r"(a[3]), "r"(b[0]), "r"(b[1]));
}

// ---------------------------------------------------------------------------
// One 128x128 tile: MMA mainloop + exp epilogue + partial writes.
// ---------------------------------------------------------------------------
__device__ __forceinline__ void do_tile(const __half* As, const __half* Bs,
                                        float* red, float* colred,
                                        int it, int jt, int i0, int j0, bool diag,
                                        int wm, int wn, int lane, int tid) {
    float c[2][8][4];
    #pragma unroll
    for (int a = 0; a < 2; a++)
        #pragma unroll
        for (int bq = 0; bq < 8; bq++)
            #pragma unroll
            for (int e = 0; e < 4; e++) c[a][bq][e] = 0.f;

    #pragma unroll
    for (int ks = 0; ks < DIM; ks += 16) {
        uint32_t af[2][4];
        #pragma unroll
        for (int mt = 0; mt < 2; mt++) {
            int row = wm * 32 + mt * 16 + (lane & 15);
            int col = ks + 8 * (lane >> 4);
            uint32_t addr = (uint32_t)__cvta_generic_to_shared(As + row * LDS + col);
            ldsm_x4(addr, af[mt][0], af[mt][1], af[mt][2], af[mt][3]);
        }
        uint32_t bf[8][2];
        #pragma unroll
        for (int np = 0; np < 4; np++) {
            int quad = lane >> 3, within = lane & 7;
            int n = wn * 64 + np * 16 + (quad >> 1) * 8 + within;
            int k = ks + (quad & 1) * 8;
            uint32_t addr = (uint32_t)__cvta_generic_to_shared(Bs + n * LDS + k);
            uint32_t r0, r1, r2, r3;
            ldsm_x4(addr, r0, r1, r2, r3);
            bf[np * 2][0] = r0;     bf[np * 2][1] = r1;
            bf[np * 2 + 1][0] = r2; bf[np * 2 + 1][1] = r3;
        }
        #pragma unroll
        for (int mt = 0; mt < 2; mt++)
            #pragma unroll
            for (int nt = 0; nt < 8; nt++)
                mma16816(c[mt][nt], af[mt], bf[nt]);
    }

    // Epilogue: ev = exp(2*sim); row sums + column sums.
    float rowsum[4] = {0.f, 0.f, 0.f, 0.f};
    float colacc[16];
    #pragma unroll
    for (int q = 0; q < 16; q++) colacc[q] = 0.f;

    #pragma unroll
    for (int mt = 0; mt < 2; mt++) {
        #pragma unroll
        for (int nt = 0; nt < 8; nt++) {
            #pragma unroll
            for (int rh = 0; rh < 2; rh++) {
                #pragma unroll
                for (int e = 0; e < 2; e++) {
                    float v = c[mt][nt][rh * 2 + e];
                    float ev = __expf(2.0f * v);
                    if (diag) {
                        int lrow = wm * 32 + mt * 16 + rh * 8 + (lane >> 2);
                        int lcol = wn * 64 + nt * 8 + (lane & 3) * 2 + e;
                        if (lrow == lcol) ev = 0.f;
                    }
                    rowsum[mt * 2 + rh] += ev;
                    colacc[nt * 2 + e]  += ev;
                }
            }
        }
    }

    #pragma unroll
    for (int mt = 0; mt < 2; mt++) {
        #pragma unroll
        for (int rh = 0; rh < 2; rh++) {
            float s = rowsum[mt * 2 + rh];
            s += __shfl_xor_sync(0xffffffffu, s, 1);
            s += __shfl_xor_sync(0xffffffffu, s, 2);
            if ((lane & 3) == 0) {
                int lrow = wm * 32 + mt * 16 + rh * 8 + (lane >> 2);
                red[wn * BM + lrow] = s;
            }
        }
    }
    #pragma unroll
    for (int q = 0; q < 16; q++) {
        float s = colacc[q];
        s += __shfl_xor_sync(0xffffffffu, s, 4);
        s += __shfl_xor_sync(0xffffffffu, s, 8);
        s += __shfl_xor_sync(0xffffffffu, s, 16);
        colacc[q] = s;
    }
    if (lane < 4) {
        #pragma unroll
        for (int q = 0; q < 16; q++) {
            int lcol = wn * 64 + (q >> 1) * 8 + lane * 2 + (q & 1);
            colred[wm * BN + lcol] = colacc[q];
        }
    }
    __syncthreads();

    if (tid < BM)
        g_partial[jt * N_TOT + i0 + tid] = red[tid] + red[BM + tid];
    if (!diag && tid < BN)
        g_partial[it * N_TOT + j0 + tid] =
            colred[tid] + colred[BN + tid] + colred[2 * BN + tid] + colred[3 * BN + tid];
    __syncthreads();   // protect red/colred before a second tile reuses them
}

// ---------------------------------------------------------------------------
// Kernel 2: paired j-tiles. Grid (32, 64): it = y, jt0 = it + 2x, jt1 = jt0+1.
// A staged once per block, shared by both j-tiles (-25% L2 staging traffic).
// ---------------------------------------------------------------------------
__global__ void __launch_bounds__(256, 2) k_simexp() {
    const int it  = blockIdx.y;
    const int jt0 = it + 2 * blockIdx.x;
    if (jt0 >= NJT) return;
    const int jt1 = jt0 + 1;
    const bool valid1 = (jt1 < NJT);

    extern __shared__ char smem[];
    __half* As  = (__half*)(smem + SM_A);
    __half* Bs0 = (__half*)(smem + SM_B0);
    __half* Bs1 = (__half*)(smem + SM_B1);
    float*  red    = (float*)(smem + SM_RED);
    float*  colred = (float*)(smem + SM_CRED);

    const int i0 = it * BM, j00 = jt0 * BN, j01 = jt1 * BN;
    const int tid  = threadIdx.x;
    const int warp = tid >> 5, lane = tid & 31;
    const int wm = warp >> 1, wn = warp & 1;

    // Stage A + B0 (+ B1): 128 rows x 16 x 8-half segments each.
    #pragma unroll
    for (int s = 0; s < 8; s++) {
        int idx = tid + 256 * s;
        int row = idx >> 4, seg = idx & 15;
        *(float4*)(As + row * LDS + seg * 8) =
            *(const float4*)(g_zn_h + (i0 + row) * DIM + seg * 8);
        *(float4*)(Bs0 + row * LDS + seg * 8) =
            *(const float4*)(g_zn_h + (j00 + row) * DIM + seg * 8);
        if (valid1)
            *(float4*)(Bs1 + row * LDS + seg * 8) =
                *(const float4*)(g_zn_h + (j01 + row) * DIM + seg * 8);
    }
    __syncthreads();

    do_tile(As, Bs0, red, colred, it, jt0, i0, j00, jt0 == it, wm, wn, lane, tid);
    if (valid1)
        do_tile(As, Bs1, red, colred, it, jt1, i0, j01, false, wm, wn, lane, tid);
}

// ---------------------------------------------------------------------------
// Kernel 3: S-sum + log - pos + block sum + last-block final mean.
// Grid 64 x 256; block owns 128 consecutive rows.
// ---------------------------------------------------------------------------
__global__ void __launch_bounds__(256) k_loss(float* __restrict__ out) {
    __shared__ float sS[2][128];
    __shared__ float lred[4];
    __shared__ bool  amLast;
    const int tid = threadIdx.x, lane = tid & 31, warp = tid >> 5;
    const int i0 = blockIdx.x * 128;

    // Phase 1: S partials, coalesced (lane <-> row).
    {
        int rloc = tid & 127, half = tid >> 7;
        int r = i0 + rloc;
        float s = 0.f;
        #pragma unroll
        for (int t = 0; t < 32; t++)
            s += g_partial[(half * 32 + t) * N_TOT + r];
        sS[half][rloc] = s;
    }
    __syncthreads();

    // Phase 2: per-row loss, then warp-reduce (4 active warps).
    float l = 0.f;
    if (tid < 128) {
        int r = i0 + tid;
        float S = sS[0][tid] + sS[1][tid];
        l = logf(S) - g_pos[r & (B_HALF - 1)];
    }
    #pragma unroll
    for (int o = 16; o; o >>= 1) l += __shfl_xor_sync(0xffffffffu, l, o);
    if (tid < 128 && lane == 0) lred[warp] = l;
    __syncthreads();

    if (warp == 0) {
        float s = (lane < 4) ? lred[lane] : 0.f;
        #pragma unroll
        for (int o = 2; o; o >>= 1) s += __shfl_xor_sync(0xffffffffu, s, o);
        if (lane == 0) {
            g_bsum[blockIdx.x] = s;
            __threadfence();
            amLast = (atomicAdd(&g_done, 1) == 63);
        }
    }
    __syncthreads();

    // Last block: deterministic fixed-order sum of the 64 block results.
    if (amLast && warp == 0) {
        float s = g_bsum[lane] + g_bsum[lane + 32];
        #pragma unroll
        for (int o = 16; o; o >>= 1) s += __shfl_xor_sync(0xffffffffu, s, o);
        if (lane == 0) out[0] = s / (float)N_TOT;
    }
}

// ---------------------------------------------------------------------------
extern "C" void kernel_launch(void* const* d_in, const int* in_sizes, int n_in,
                              void* d_out, int out_size) {
    const float* zi = (const float*)d_in[0];
    const float* zj = (const float*)d_in[1];
    (void)in_sizes; (void)n_in; (void)out_size;

    cudaFuncSetAttribute(k_simexp, cudaFuncAttributeMaxDynamicSharedMemorySize, SMEM_SZ);

    k_normalize<<<B_HALF / 8, 256>>>(zi, zj);
    dim3 grid(NJT / 2, NJT);
    k_simexp<<<grid, 256, SMEM_SZ>>>();
    k_loss<<<64, 256>>>((float*)d_out);
}